// round 6
// baseline (speedup 1.0000x reference)
#include <cuda_runtime.h>
#include <cstdint>

// out = (x != corner_of_plane) ? 1.0f : 0.0f
// x: (16, 3, 1024, 1024) fp32, plane = 1<<20 elements (262144 float4s).
// Persistent grid-stride streamer: single wave (148 SMs x 8 CTAs), each CTA
// loops over tiles of 1024 float4s. __ldcs reads / __stcs stores (measured
// best store policy). Tile is 1024-float4 aligned -> always within one plane.

#define THREADS 256
#define UNROLL 4
#define TILE_F4 (THREADS * UNROLL)   // 1024 float4s per tile
#define GRID_BLOCKS 1184             // 148 SMs * 8 resident CTAs

__global__ void __launch_bounds__(THREADS) remover_kernel(
    const float* __restrict__ x,
    float* __restrict__ out,
    long long n_tiles) {

    const float4* __restrict__ x4 = reinterpret_cast<const float4*>(x);
    float4* __restrict__ out4 = reinterpret_cast<float4*>(out);

    for (long long tile = blockIdx.x; tile < n_tiles; tile += gridDim.x) {
        long long tile_base = tile * TILE_F4;            // float4 index
        long long base = tile_base + threadIdx.x;

        // plane = element_idx >> 20 = float4_idx >> 18; uniform per tile.
        long long plane = tile_base >> 18;
        float corner = __ldg(x + (plane << 20));

        float4 v[UNROLL];
#pragma unroll
        for (int u = 0; u < UNROLL; u++) {
            v[u] = __ldcs(x4 + base + (long long)u * THREADS);
        }

#pragma unroll
        for (int u = 0; u < UNROLL; u++) {
            float4 r;
            r.x = (v[u].x != corner) ? 1.0f : 0.0f;
            r.y = (v[u].y != corner) ? 1.0f : 0.0f;
            r.z = (v[u].z != corner) ? 1.0f : 0.0f;
            r.w = (v[u].w != corner) ? 1.0f : 0.0f;
            __stcs(out4 + base + (long long)u * THREADS, r);
        }
    }
}

extern "C" void kernel_launch(void* const* d_in, const int* in_sizes, int n_in,
                              void* d_out, int out_size) {
    const float* x = (const float*)d_in[0];
    float* out = (float*)d_out;

    long long n = (long long)in_sizes[0];      // 50331648
    long long n4 = n >> 2;                     // 12582912 float4s
    long long n_tiles = n4 / TILE_F4;          // 12288, exact

    remover_kernel<<<GRID_BLOCKS, THREADS>>>(x, out, n_tiles);
}

// round 7
// speedup vs baseline: 1.0698x; 1.0698x over previous
#include <cuda_runtime.h>
#include <cstdint>

// out = (x != corner_of_plane) ? 1.0f : 0.0f
// x: (16, 3, 1024, 1024) fp32, plane = 1<<20 elements (262144 float4s).
// HBM-streaming at measured R/W ceiling (~6.28 TB/s). Best-measured policy:
// __ldcs reads + __stcs stores. Shape probe: 512 threads x U4 (full occupancy,
// MLP=4, half the CTAs of the 256-thread variant).

#define THREADS 512
#define UNROLL 4
#define TILE_F4 (THREADS * UNROLL)   // 2048 float4s per block

__global__ void __launch_bounds__(THREADS) remover_kernel(
    const float* __restrict__ x,
    float* __restrict__ out) {

    const float4* __restrict__ x4 = reinterpret_cast<const float4*>(x);
    float4* __restrict__ out4 = reinterpret_cast<float4*>(out);

    long long tile_base = (long long)blockIdx.x * TILE_F4;
    long long base = tile_base + threadIdx.x;

    // Block tile (2048 float4s) always lies within one plane (262144 float4s).
    // plane = element_idx >> 20 = float4_idx >> 18 — uniform across the block.
    long long plane = tile_base >> 18;
    float corner = __ldg(x + (plane << 20));

    float4 v[UNROLL];
#pragma unroll
    for (int u = 0; u < UNROLL; u++) {
        v[u] = __ldcs(x4 + base + (long long)u * THREADS);
    }

#pragma unroll
    for (int u = 0; u < UNROLL; u++) {
        float4 r;
        r.x = (v[u].x != corner) ? 1.0f : 0.0f;
        r.y = (v[u].y != corner) ? 1.0f : 0.0f;
        r.z = (v[u].z != corner) ? 1.0f : 0.0f;
        r.w = (v[u].w != corner) ? 1.0f : 0.0f;
        __stcs(out4 + base + (long long)u * THREADS, r);
    }
}

extern "C" void kernel_launch(void* const* d_in, const int* in_sizes, int n_in,
                              void* d_out, int out_size) {
    const float* x = (const float*)d_in[0];
    float* out = (float*)d_out;

    long long n = (long long)in_sizes[0];                 // 50331648
    long long n4 = n >> 2;                                // 12582912 float4s
    long long blocks = (n4 + TILE_F4 - 1) / TILE_F4;      // 6144, exact fit

    remover_kernel<<<(unsigned)blocks, THREADS>>>(x, out);
}